// round 14
// baseline (speedup 1.0000x reference)
#include <cuda_runtime.h>
#include <cuda_bf16.h>
#include <cstdint>
#include <cfloat>
#include <math.h>

#define VV 100000
#define EE 128
#define BB 2048
#define NBX 782            // ceil(V / 128) col tiles
#define LROW 144           // smem row stride bytes (128B data + 16B pad)
#define NCHUNK 8           // 2 row-blocks (256 rows) per chunk

// ---- scratch (device globals: allocation-free) ----
__device__ __align__(16) uint8_t g_emb8[BB * EE];                  // fp8 e4m3, x64
__device__ __align__(16) uint8_t g_wout8[(size_t)VV * EE];         // fp8 e4m3, x64
__device__ __align__(16) __nv_bfloat16 g_logits[(size_t)BB * VV];  // 409.6 MB
__device__ __align__(16) float g_ps[(size_t)BB * NBX];             // sum-exp partials
__device__ float g_lse[BB];

#define INV_SCALE (1.0f / 4096.0f)
#define NW4 (VV * EE / 4)
#define NE4 (BB * EE / 4)

__device__ __forceinline__ uint32_t smem_u32(const void* p) {
    uint32_t a;
    asm("{ .reg .u64 t; cvta.to.shared.u64 t, %1; cvt.u32.u64 %0, t; }" : "=r"(a) : "l"(p));
    return a;
}
__device__ __forceinline__ void ldsm4(uint32_t* r, uint32_t addr) {
    asm volatile("ldmatrix.sync.aligned.m8n8.x4.shared.b16 {%0,%1,%2,%3}, [%4];"
                 : "=r"(r[0]), "=r"(r[1]), "=r"(r[2]), "=r"(r[3]) : "r"(addr));
}
__device__ __forceinline__ void cpasync16(uint32_t dst, const void* src, int src_bytes) {
    asm volatile("cp.async.cg.shared.global [%0], [%1], 16, %2;"
                 :: "r"(dst), "l"(src), "r"(src_bytes));
}
__device__ __forceinline__ uint16_t fp8x2(float lo, float hi) {
    uint16_t r;
    asm("cvt.rn.satfinite.e4m3x2.f32 %0, %1, %2;" : "=h"(r) : "f"(hi), "f"(lo));
    return r;
}

// ---- K0: fused convert (W_out -> fp8) + gather (emb -> fp8) ----
__global__ void convert_all(const float* __restrict__ w,
                            const void* __restrict__ cw_raw,
                            const float* __restrict__ Wc,
                            const float* __restrict__ bc) {
    int i = blockIdx.x * blockDim.x + threadIdx.x;
    if (i < NW4) {
        float4 v = ((const float4*)w)[i];
        uint32_t lo = fp8x2(v.x * 64.f, v.y * 64.f);
        uint32_t hi = fp8x2(v.z * 64.f, v.w * 64.f);
        ((uint32_t*)g_wout8)[i] = lo | (hi << 16);
    } else if (i < NW4 + NE4) {
        int j = i - NW4;
        const int* wi = (const int*)cw_raw;
        bool is64 = ((wi[1] | wi[3] | wi[5] | wi[7] | wi[9] | wi[11] | wi[13] | wi[15]) == 0);
        int b = j >> 5, e0 = (j & 31) * 4;
        int idx = is64 ? wi[2 * b] : wi[b];
        float f[4];
        #pragma unroll
        for (int k = 0; k < 4; k++)
            f[k] = (Wc[(size_t)(e0 + k) * VV + idx] + bc[e0 + k]) * 64.f;
        uint32_t lo = fp8x2(f[0], f[1]);
        uint32_t hi = fp8x2(f[2], f[3]);
        ((uint32_t*)g_emb8)[j] = lo | (hi << 16);
    }
}

// ---- K2: fp8 GEMM 128x128xK128; bf16 logits + one sum-exp partial per (row, CTA) ----
__global__ __launch_bounds__(256, 2) void gemm_fp8(const float* __restrict__ b_out, int rb0) {
    extern __shared__ uint8_t sm[];
    __shared__ float sbias[128];
    const uint32_t sA = smem_u32(sm);
    const uint32_t sB = sA + 128 * LROW;
    float* sred = (float*)sm;

    const int bx = blockIdx.x;
    const int rbv = rb0 + blockIdx.y;
    const int tid = threadIdx.x;
    const int warp = tid >> 5, lane = tid & 31;
    const int wm = warp >> 2, wn = warp & 3;
    const int g = lane >> 2, q = lane & 3;

    #pragma unroll
    for (int it = 0; it < 4; it++) {
        int chunk = it * 256 + tid;
        int r = chunk >> 3;
        int c = (chunk & 7) * 16;
        cpasync16(sA + r * LROW + c, &g_emb8[(size_t)(rbv * 128 + r) * 128 + c], 16);
        int v = bx * 128 + r;
        cpasync16(sB + r * LROW + c, &g_wout8[(size_t)(v < VV ? v : 0) * 128 + c],
                  (v < VV) ? 16 : 0);
    }
    if (tid < 128) {
        int col = bx * 128 + tid;
        sbias[tid] = (col < VV) ? b_out[col] : 0.f;
    }
    asm volatile("cp.async.commit_group;");
    asm volatile("cp.async.wait_group 0;");
    __syncthreads();

    float acc[4][4][4];
    #pragma unroll
    for (int a = 0; a < 4; a++)
        #pragma unroll
        for (int b = 0; b < 4; b++)
            #pragma unroll
            for (int c = 0; c < 4; c++) acc[a][b][c] = 0.f;

    const int arow = wm * 64 + (lane & 15);
    const int brow = wn * 32 + ((lane >> 4) << 3) + (lane & 7);
    const int acolu = (lane >> 4) * 8;
    const int bcolu = ((lane >> 3) & 1) * 8;

    #pragma unroll
    for (int kk = 0; kk < 4; kk++) {
        uint32_t af[4][4], bf[2][4];
        #pragma unroll
        for (int mi = 0; mi < 4; mi++)
            ldsm4(af[mi], sA + (arow + mi * 16) * LROW + (kk * 16 + acolu) * 2);
        #pragma unroll
        for (int gi = 0; gi < 2; gi++)
            ldsm4(bf[gi], sB + (brow + gi * 16) * LROW + (kk * 16 + bcolu) * 2);
        #pragma unroll
        for (int mi = 0; mi < 4; mi++)
            #pragma unroll
            for (int ni = 0; ni < 4; ni++) {
                uint32_t b0 = bf[ni >> 1][(ni & 1) * 2];
                uint32_t b1 = bf[ni >> 1][(ni & 1) * 2 + 1];
                asm volatile(
                    "mma.sync.aligned.m16n8k32.row.col.f32.e4m3.e4m3.f32 "
                    "{%0,%1,%2,%3}, {%4,%5,%6,%7}, {%8,%9}, {%0,%1,%2,%3};"
                    : "+f"(acc[mi][ni][0]), "+f"(acc[mi][ni][1]),
                      "+f"(acc[mi][ni][2]), "+f"(acc[mi][ni][3])
                    : "r"(af[mi][0]), "r"(af[mi][1]), "r"(af[mi][2]), "r"(af[mi][3]),
                      "r"(b0), "r"(b1));
            }
    }

    float bo[4][2]; bool okc[4]; int cols[4];
    #pragma unroll
    for (int ni = 0; ni < 4; ni++) {
        int lcol = wn * 32 + ni * 8 + q * 2;
        int col = bx * 128 + lcol;
        cols[ni] = col;
        okc[ni] = (col < VV);
        bo[ni][0] = sbias[lcol];
        bo[ni][1] = sbias[lcol + 1];
    }

    float rs[4][2];
    #pragma unroll
    for (int mi = 0; mi < 4; mi++) {
        #pragma unroll
        for (int rg = 0; rg < 2; rg++) {
            int grow = rbv * 128 + wm * 64 + mi * 16 + rg * 8 + g;
            __nv_bfloat16* lp = g_logits + (size_t)grow * VV;
            float s = 0.f;
            #pragma unroll
            for (int ni = 0; ni < 4; ni++) {
                if (okc[ni]) {
                    float v0 = fmaf(acc[mi][ni][rg * 2 + 0], INV_SCALE, bo[ni][0]);
                    float v1 = fmaf(acc[mi][ni][rg * 2 + 1], INV_SCALE, bo[ni][1]);
                    *(__nv_bfloat162*)&lp[cols[ni]] = __floats2bfloat162_rn(v0, v1);
                    s += __expf(v0) + __expf(v1);
                }
            }
            rs[mi][rg] = s;
        }
    }

    __syncthreads();
    #pragma unroll
    for (int mi = 0; mi < 4; mi++)
        #pragma unroll
        for (int rg = 0; rg < 2; rg++) {
            int within = mi * 16 + rg * 8 + g;
            sred[((wm * 4 + wn) * 64 + within) * 4 + q] = rs[mi][rg];
        }
    __syncthreads();
    if (tid < 128) {
        int wmc = tid >> 6, within = tid & 63;
        float s = 0.f;
        #pragma unroll
        for (int w2 = 0; w2 < 4; w2++)
            #pragma unroll
            for (int qq = 0; qq < 4; qq++)
                s += sred[((wmc * 4 + w2) * 64 + within) * 4 + qq];
        int grow = rbv * 128 + wmc * 64 + within;
        g_ps[(size_t)grow * NBX + bx] = s;
    }
}

// ---- K3: lse[row] = log(sum of partials) ----
__global__ void reduce_lse(int row0) {
    int row = row0 + blockIdx.x;
    int tid = threadIdx.x;   // 256
    float s = 0.f;
    const float* p = &g_ps[(size_t)row * NBX];
    for (int j = tid; j < NBX; j += 256) s += p[j];
    __shared__ float ss_[256];
    ss_[tid] = s;
    __syncthreads();
    for (int off = 128; off > 0; off >>= 1) {
        if (tid < off) ss_[tid] += ss_[tid + off];
        __syncthreads();
    }
    if (tid == 0) g_lse[row] = logf(ss_[0]);
}

// ---- K4: out = bf16_logits - lse  (reads hot L2 chunk; streaming writes) ----
__global__ void finalize(float* __restrict__ out, int row0) {
    int j = blockIdx.x * blockDim.x + threadIdx.x;   // uint4 chunk (8 bf16)
    int row = row0 + blockIdx.y;
    const int nch = VV / 8;  // 12500
    if (j < nch) {
        float l = g_lse[row];
        uint4 v = __ldcs((const uint4*)(g_logits + (size_t)row * VV) + j);
        const __nv_bfloat162* p = (const __nv_bfloat162*)&v;
        float* op = out + (size_t)row * VV + j * 8;
        float4 o0, o1;
        float2 f;
        f = __bfloat1622float2(p[0]); o0.x = f.x - l; o0.y = f.y - l;
        f = __bfloat1622float2(p[1]); o0.z = f.x - l; o0.w = f.y - l;
        f = __bfloat1622float2(p[2]); o1.x = f.x - l; o1.y = f.y - l;
        f = __bfloat1622float2(p[3]); o1.z = f.x - l; o1.w = f.y - l;
        __stcs((float4*)op, o0);
        __stcs((float4*)op + 1, o1);
    }
}

extern "C" void kernel_launch(void* const* d_in, const int* in_sizes, int n_in,
                              void* d_out, int out_size) {
    const void*  cw = d_in[0];
    const float* Wc = (const float*)d_in[1];
    const float* bc = (const float*)d_in[2];
    const float* Wo = (const float*)d_in[3];
    const float* bo = (const float*)d_in[4];
    float* out = (float*)d_out;

    const int smem = 2 * 128 * LROW;   // 36864
    cudaFuncSetAttribute(gemm_fp8, cudaFuncAttributeMaxDynamicSharedMemorySize, smem);

    const int fgx = (VV / 8 + 255) / 256;   // 49

    convert_all<<<(NW4 + NE4 + 255) / 256, 256>>>(Wo, cw, Wc, bc);

    // chunked: gemm writes 51.2MB of logits, finalize reads them while L2-hot
    for (int c = 0; c < NCHUNK; c++) {
        gemm_fp8<<<dim3(NBX, 2), 256, smem>>>(bo, c * 2);
        reduce_lse<<<256, 256>>>(c * 256);
        finalize<<<dim3(fgx, 256), 256>>>(out, c * 256);
    }
}

// round 15
// speedup vs baseline: 1.2135x; 1.2135x over previous
#include <cuda_runtime.h>
#include <cuda_bf16.h>
#include <cstdint>
#include <cfloat>
#include <math.h>

#define VV 100000
#define EE 128
#define BB 2048
#define NBX 782            // ceil(V / 128) col tiles
#define LROW 144           // smem row stride bytes (tile loads)
#define SROW 272           // smem row stride bytes (logits staging; bank-conflict-free)
#define SRED_OFF 34816     // staging = 128*272 = 34816; sred after it
#define SM_TOTAL (34816 + 8192)   // 43008

// ---- scratch (device globals: allocation-free) ----
__device__ __align__(16) uint8_t g_emb8[BB * EE];                  // fp8 e4m3, x64
__device__ __align__(16) uint8_t g_wout8[(size_t)VV * EE];         // fp8 e4m3, x64
__device__ __align__(16) __nv_bfloat16 g_logits[(size_t)BB * VV];  // 409.6 MB
__device__ __align__(16) float g_ps[(size_t)BB * NBX];             // sum-exp partials
__device__ float g_lse[BB];

#define INV_SCALE (1.0f / 4096.0f)
#define NW4 (VV * EE / 4)
#define NE4 (BB * EE / 4)

__device__ __forceinline__ uint32_t smem_u32(const void* p) {
    uint32_t a;
    asm("{ .reg .u64 t; cvta.to.shared.u64 t, %1; cvt.u32.u64 %0, t; }" : "=r"(a) : "l"(p));
    return a;
}
__device__ __forceinline__ void ldsm4(uint32_t* r, uint32_t addr) {
    asm volatile("ldmatrix.sync.aligned.m8n8.x4.shared.b16 {%0,%1,%2,%3}, [%4];"
                 : "=r"(r[0]), "=r"(r[1]), "=r"(r[2]), "=r"(r[3]) : "r"(addr));
}
__device__ __forceinline__ void cpasync16(uint32_t dst, const void* src, int src_bytes) {
    asm volatile("cp.async.cg.shared.global [%0], [%1], 16, %2;"
                 :: "r"(dst), "l"(src), "r"(src_bytes));
}
__device__ __forceinline__ uint16_t fp8x2(float lo, float hi) {
    uint16_t r;
    asm("cvt.rn.satfinite.e4m3x2.f32 %0, %1, %2;" : "=h"(r) : "f"(hi), "f"(lo));
    return r;
}

// ---- K0: fused convert (W_out -> fp8) + gather (emb -> fp8) ----
__global__ void convert_all(const float* __restrict__ w,
                            const void* __restrict__ cw_raw,
                            const float* __restrict__ Wc,
                            const float* __restrict__ bc) {
    int i = blockIdx.x * blockDim.x + threadIdx.x;
    if (i < NW4) {
        float4 v = ((const float4*)w)[i];
        uint32_t lo = fp8x2(v.x * 64.f, v.y * 64.f);
        uint32_t hi = fp8x2(v.z * 64.f, v.w * 64.f);
        ((uint32_t*)g_wout8)[i] = lo | (hi << 16);
    } else if (i < NW4 + NE4) {
        int j = i - NW4;
        const int* wi = (const int*)cw_raw;
        bool is64 = ((wi[1] | wi[3] | wi[5] | wi[7] | wi[9] | wi[11] | wi[13] | wi[15]) == 0);
        int b = j >> 5, e0 = (j & 31) * 4;
        int idx = is64 ? wi[2 * b] : wi[b];
        float f[4];
        #pragma unroll
        for (int k = 0; k < 4; k++)
            f[k] = (Wc[(size_t)(e0 + k) * VV + idx] + bc[e0 + k]) * 64.f;
        uint32_t lo = fp8x2(f[0], f[1]);
        uint32_t hi = fp8x2(f[2], f[3]);
        ((uint32_t*)g_emb8)[j] = lo | (hi << 16);
    }
}

// ---- K2: fp8 GEMM 128x128xK128; staged coalesced bf16 logits + partials ----
__global__ __launch_bounds__(256, 2) void gemm_fp8(const float* __restrict__ b_out) {
    extern __shared__ uint8_t sm[];
    __shared__ float sbias[128];
    const uint32_t sA = smem_u32(sm);
    const uint32_t sB = sA + 128 * LROW;
    float* sred = (float*)(sm + SRED_OFF);

    const int bx = blockIdx.x, by = blockIdx.y;
    const int tid = threadIdx.x;
    const int warp = tid >> 5, lane = tid & 31;
    const int wm = warp >> 2, wn = warp & 3;
    const int g = lane >> 2, q = lane & 3;

    #pragma unroll
    for (int it = 0; it < 4; it++) {
        int chunk = it * 256 + tid;
        int r = chunk >> 3;
        int c = (chunk & 7) * 16;
        cpasync16(sA + r * LROW + c, &g_emb8[(size_t)(by * 128 + r) * 128 + c], 16);
        int v = bx * 128 + r;
        cpasync16(sB + r * LROW + c, &g_wout8[(size_t)(v < VV ? v : 0) * 128 + c],
                  (v < VV) ? 16 : 0);
    }
    if (tid < 128) {
        int col = bx * 128 + tid;
        sbias[tid] = (col < VV) ? b_out[col] : 0.f;
    }
    asm volatile("cp.async.commit_group;");
    asm volatile("cp.async.wait_group 0;");
    __syncthreads();

    float acc[4][4][4];
    #pragma unroll
    for (int a = 0; a < 4; a++)
        #pragma unroll
        for (int b = 0; b < 4; b++)
            #pragma unroll
            for (int c = 0; c < 4; c++) acc[a][b][c] = 0.f;

    const int arow = wm * 64 + (lane & 15);
    const int brow = wn * 32 + ((lane >> 4) << 3) + (lane & 7);
    const int acolu = (lane >> 4) * 8;
    const int bcolu = ((lane >> 3) & 1) * 8;

    #pragma unroll
    for (int kk = 0; kk < 4; kk++) {
        uint32_t af[4][4], bf[2][4];
        #pragma unroll
        for (int mi = 0; mi < 4; mi++)
            ldsm4(af[mi], sA + (arow + mi * 16) * LROW + (kk * 16 + acolu) * 2);
        #pragma unroll
        for (int gi = 0; gi < 2; gi++)
            ldsm4(bf[gi], sB + (brow + gi * 16) * LROW + (kk * 16 + bcolu) * 2);
        #pragma unroll
        for (int mi = 0; mi < 4; mi++)
            #pragma unroll
            for (int ni = 0; ni < 4; ni++) {
                uint32_t b0 = bf[ni >> 1][(ni & 1) * 2];
                uint32_t b1 = bf[ni >> 1][(ni & 1) * 2 + 1];
                asm volatile(
                    "mma.sync.aligned.m16n8k32.row.col.f32.e4m3.e4m3.f32 "
                    "{%0,%1,%2,%3}, {%4,%5,%6,%7}, {%8,%9}, {%0,%1,%2,%3};"
                    : "+f"(acc[mi][ni][0]), "+f"(acc[mi][ni][1]),
                      "+f"(acc[mi][ni][2]), "+f"(acc[mi][ni][3])
                    : "r"(af[mi][0]), "r"(af[mi][1]), "r"(af[mi][2]), "r"(af[mi][3]),
                      "r"(b0), "r"(b1));
            }
    }

    __syncthreads();   // done reading A/B tiles; smem is reusable

    if (bx != NBX - 1) {
        // ---- fast path: full tile, staged coalesced stores ----
        #pragma unroll
        for (int mi = 0; mi < 4; mi++) {
            #pragma unroll
            for (int rg = 0; rg < 2; rg++) {
                int lrow = wm * 64 + mi * 16 + rg * 8 + g;
                float s = 0.f;
                #pragma unroll
                for (int ni = 0; ni < 4; ni++) {
                    int lcol = wn * 32 + ni * 8 + q * 2;
                    float v0 = fmaf(acc[mi][ni][rg * 2 + 0], INV_SCALE, sbias[lcol]);
                    float v1 = fmaf(acc[mi][ni][rg * 2 + 1], INV_SCALE, sbias[lcol + 1]);
                    *(__nv_bfloat162*)(sm + lrow * SROW + lcol * 2) =
                        __floats2bfloat162_rn(v0, v1);
                    s += __expf(v0) + __expf(v1);
                }
                sred[((wm * 4 + wn) * 64 + mi * 16 + rg * 8 + g) * 4 + q] = s;
            }
        }
        __syncthreads();
        // coalesced 16B stores of the staged tile
        #pragma unroll
        for (int i = 0; i < 8; i++) {
            int c = i * 256 + tid;            // 0..2047
            int lrow = c >> 4;
            int off = (c & 15) * 16;
            uint4 v = *(uint4*)(sm + lrow * SROW + off);
            int grow = by * 128 + lrow;
            *(uint4*)((char*)(g_logits + (size_t)grow * VV) + (size_t)bx * 256 + off) = v;
        }
        if (tid < 128) {
            int wmc = tid >> 6, within = tid & 63;
            float s = 0.f;
            #pragma unroll
            for (int w2 = 0; w2 < 4; w2++)
                #pragma unroll
                for (int qq = 0; qq < 4; qq++)
                    s += sred[((wmc * 4 + w2) * 64 + within) * 4 + qq];
            int grow = by * 128 + wmc * 64 + within;
            g_ps[(size_t)grow * NBX + bx] = s;
        }
    } else {
        // ---- edge tile: guarded scattered stores (16 CTAs total) ----
        #pragma unroll
        for (int mi = 0; mi < 4; mi++) {
            #pragma unroll
            for (int rg = 0; rg < 2; rg++) {
                int grow = by * 128 + wm * 64 + mi * 16 + rg * 8 + g;
                __nv_bfloat16* lp = g_logits + (size_t)grow * VV;
                float s = 0.f;
                #pragma unroll
                for (int ni = 0; ni < 4; ni++) {
                    int lcol = wn * 32 + ni * 8 + q * 2;
                    int col = bx * 128 + lcol;
                    if (col < VV) {
                        float v0 = fmaf(acc[mi][ni][rg * 2 + 0], INV_SCALE, sbias[lcol]);
                        float v1 = fmaf(acc[mi][ni][rg * 2 + 1], INV_SCALE, sbias[lcol + 1]);
                        *(__nv_bfloat162*)&lp[col] = __floats2bfloat162_rn(v0, v1);
                        s += __expf(v0) + __expf(v1);
                    }
                }
                sred[((wm * 4 + wn) * 64 + mi * 16 + rg * 8 + g) * 4 + q] = s;
            }
        }
        __syncthreads();
        if (tid < 128) {
            int wmc = tid >> 6, within = tid & 63;
            float s = 0.f;
            #pragma unroll
            for (int w2 = 0; w2 < 4; w2++)
                #pragma unroll
                for (int qq = 0; qq < 4; qq++)
                    s += sred[((wmc * 4 + w2) * 64 + within) * 4 + qq];
            int grow = by * 128 + wmc * 64 + within;
            g_ps[(size_t)grow * NBX + bx] = s;
        }
    }
}

// ---- K3: lse[row] = log(sum of partials) ----
__global__ void reduce_lse() {
    int row = blockIdx.x;
    int tid = threadIdx.x;   // 256
    float s = 0.f;
    const float* p = &g_ps[(size_t)row * NBX];
    for (int j = tid; j < NBX; j += 256) s += p[j];
    __shared__ float ss_[256];
    ss_[tid] = s;
    __syncthreads();
    for (int off = 128; off > 0; off >>= 1) {
        if (tid < off) ss_[tid] += ss_[tid + off];
        __syncthreads();
    }
    if (tid == 0) g_lse[row] = logf(ss_[0]);
}

// ---- K4: out = bf16_logits - lse (streaming hints) ----
__global__ void finalize(float* __restrict__ out) {
    int j = blockIdx.x * blockDim.x + threadIdx.x;   // uint4 chunk (8 bf16)
    int row = blockIdx.y;
    const int nch = VV / 8;  // 12500
    if (j < nch) {
        float l = g_lse[row];
        uint4 v = __ldcs((const uint4*)(g_logits + (size_t)row * VV) + j);
        const __nv_bfloat162* p = (const __nv_bfloat162*)&v;
        float* op = out + (size_t)row * VV + j * 8;
        float4 o0, o1;
        float2 f;
        f = __bfloat1622float2(p[0]); o0.x = f.x - l; o0.y = f.y - l;
        f = __bfloat1622float2(p[1]); o0.z = f.x - l; o0.w = f.y - l;
        f = __bfloat1622float2(p[2]); o1.x = f.x - l; o1.y = f.y - l;
        f = __bfloat1622float2(p[3]); o1.z = f.x - l; o1.w = f.y - l;
        __stcs((float4*)op, o0);
        __stcs((float4*)op + 1, o1);
    }
}

extern "C" void kernel_launch(void* const* d_in, const int* in_sizes, int n_in,
                              void* d_out, int out_size) {
    const void*  cw = d_in[0];
    const float* Wc = (const float*)d_in[1];
    const float* bc = (const float*)d_in[2];
    const float* Wo = (const float*)d_in[3];
    const float* bo = (const float*)d_in[4];
    float* out = (float*)d_out;

    cudaFuncSetAttribute(gemm_fp8, cudaFuncAttributeMaxDynamicSharedMemorySize, SM_TOTAL);

    convert_all<<<(NW4 + NE4 + 255) / 256, 256>>>(Wo, cw, Wc, bc);
    gemm_fp8<<<dim3(NBX, BB / 128), 256, SM_TOTAL>>>(bo);
    reduce_lse<<<BB, 256>>>();
    finalize<<<dim3((VV / 8 + 255) / 256, BB), 256>>>(out);
}